// round 7
// baseline (speedup 1.0000x reference)
#include <cuda_runtime.h>
#include <cuda_bf16.h>

// Piecewise-linear log-sigmoid approximation (uniform breakpoints), v6.
//
// Flat one-shot kernel: exact-cover grid, 2 float4 per thread, both LDG.128
// issued up front (true MLP=2 per thread, fresh warps stream through via CLC).
// No grid-stride loop machinery.
//
// Index-space formulation (no branches): u = (v-x0)/h,
//   e = clamp(floor(u), -1, 64) + 1   (0..65)
//   out = Y[e] + (u - uf) * D[e]
// Guard entries: e=0 -> {x0-h, h} (exact identity for v < x0),
// e=65 -> {0,0} (zero for v >= xK).
//
// LUT: float2 {y, dy} replicated 32x, one column per lane:
//   tab[e*32 + lane] -> conflict-free LDS.64 by construction.

#define NSEG  64
#define NBRK  65
#define NTAB  66          // entries for idx = -1 .. 64

__global__ __launch_bounds__(256)
void logsig_pwl_kernel(const float* __restrict__ vals,
                       const float* __restrict__ x,
                       const float* __restrict__ y,
                       float* __restrict__ out,
                       int n4,        // number of float4 elements
                       int half)     // stride between this thread's 2 items
{
    __shared__ float2 tab[NTAB * 32];   // [entry][lane] {y, dy}
    __shared__ float  sc[2];            // x0, xK

    const int t = threadIdx.x;

    {
        const float x0 = x[0];
        const float xK = x[NBRK - 1];
        const float h  = (xK - x0) * (1.0f / NSEG);
        for (int j = t; j < NTAB * 32; j += blockDim.x) {
            int e = j >> 5;               // 0..65
            float2 ts;
            if (e == 0)            { ts.x = x0 - h; ts.y = h;    }
            else if (e == NTAB-1)  { ts.x = 0.0f;   ts.y = 0.0f; }
            else                   { ts.x = y[e-1]; ts.y = y[e] - y[e-1]; }
            tab[j] = ts;
        }
        if (t == 0) { sc[0] = x[0]; sc[1] = x[NBRK - 1]; }
    }
    __syncthreads();

    const float x0    = sc[0];
    const float xK    = sc[1];
    const float inv_h = (float)NSEG / (xK - x0);
    const float off   = -x0 * inv_h;          // u = v*inv_h + off

    const float2* __restrict__ mytab = tab + (t & 31);

    const float4* __restrict__ v4 = (const float4*)vals;
    float4* __restrict__ o4 = (float4*)out;

    #define INTERP(V, O) do {                                           \
        float u  = fmaf((V), inv_h, off);                               \
        float uf = floorf(u);                                           \
        uf = fmaxf(-1.0f, fminf(uf, 64.0f));                            \
        float fr = u - uf;             /* unclamped: extends guards */  \
        int   e  = ((int)uf + 1) << 5; /* entry * 32 */                 \
        float2 ts = mytab[e];                                           \
        (O) = fmaf(fr, ts.y, ts.x);                                     \
    } while (0)

    #define DO4(A, OA)                                                  \
        INTERP((A).x, (OA).x); INTERP((A).y, (OA).y);                   \
        INTERP((A).z, (OA).z); INTERP((A).w, (OA).w);

    const int i0 = blockIdx.x * blockDim.x + t;
    const int i1 = i0 + half;

    if (i1 < n4) {
        // fast path: both loads in flight before any use
        float4 a = __ldcs(&v4[i0]);
        float4 b = __ldcs(&v4[i1]);
        float4 oa, ob;
        DO4(a, oa); DO4(b, ob);
        __stcs(&o4[i0], oa);
        __stcs(&o4[i1], ob);
    } else if (i0 < n4) {
        float4 a = __ldcs(&v4[i0]);
        float4 oa;
        DO4(a, oa);
        __stcs(&o4[i0], oa);
    }
    #undef DO4
    #undef INTERP
}

// scalar tail kernel for n % 4 != 0 (not hit for this shape)
__global__ void logsig_tail_kernel(const float* __restrict__ vals,
                                   const float* __restrict__ x,
                                   const float* __restrict__ y,
                                   float* __restrict__ out,
                                   int start, int n)
{
    int i = start + blockIdx.x * blockDim.x + threadIdx.x;
    if (i >= n) return;
    float x0 = x[0], xK = x[NBRK - 1];
    float inv_h = (float)NSEG / (xK - x0);
    float v = vals[i];
    float u = fmaf(v, inv_h, -x0 * inv_h);
    float uf = fmaxf(-1.0f, fminf(floorf(u), 64.0f));
    int e = (int)uf + 1;
    float yv, dv;
    float h = (xK - x0) * (1.0f / NSEG);
    if (e == 0)           { yv = x0 - h; dv = h; }
    else if (e == NTAB-1) { yv = 0.0f;   dv = 0.0f; }
    else                  { yv = y[e-1]; dv = y[e] - y[e-1]; }
    out[i] = fmaf(u - uf, dv, yv);
}

extern "C" void kernel_launch(void* const* d_in, const int* in_sizes, int n_in,
                              void* d_out, int out_size)
{
    const float* vals = (const float*)d_in[0];
    const float* x    = (const float*)d_in[1];
    const float* y    = (const float*)d_in[2];
    float* out        = (float*)d_out;
    int n = in_sizes[0];

    int n4   = n >> 2;                 // float4 count
    int half = (n4 + 1) >> 1;          // items per half-partition
    int threads = 256;
    int blocks  = (half + threads - 1) / threads;
    if (blocks < 1) blocks = 1;

    logsig_pwl_kernel<<<blocks, threads>>>(vals, x, y, out, n4, half);

    int tail = n & 3;
    if (tail) {
        logsig_tail_kernel<<<1, 256>>>(vals, x, y, out, n4 << 2, n);
    }
}

// round 9
// speedup vs baseline: 1.0067x; 1.0067x over previous
#include <cuda_runtime.h>
#include <cuda_bf16.h>

// Piecewise-linear log-sigmoid approximation (uniform breakpoints), v7.
//
// Grid-stride skeleton (amortized LUT init), 8x-unrolled main loop with all
// 8 LDG.128 batched up front. __launch_bounds__(256,5) lifts the 32-reg cap
// so all 8 float4 loads stay live (true MLP=8 per thread).
//
// Index-space formulation (no branches): u = (v-x0)/h,
//   e = clamp(floor(u), -1, 64) + 1   (0..65)
//   out = Y[e] + (u - uf) * D[e]
// Guard entries: e=0 -> {x0-h, h} (exact identity for v < x0),
// e=65 -> {0,0} (zero for v >= xK).
//
// LUT: float2 {y, dy} replicated 32x, one column per lane -> conflict-free.

#define NSEG  64
#define NBRK  65
#define NTAB  66          // entries for idx = -1 .. 64

__global__ __launch_bounds__(256, 5)
void logsig_pwl_kernel(const float* __restrict__ vals,
                       const float* __restrict__ x,
                       const float* __restrict__ y,
                       float* __restrict__ out,
                       int n)
{
    __shared__ float2 tab[NTAB * 32];   // [entry][lane] {y, dy}
    __shared__ float  sc[2];            // x0, xK

    const int t = threadIdx.x;

    {
        const float x0 = x[0];
        const float xK = x[NBRK - 1];
        const float h  = (xK - x0) * (1.0f / NSEG);
        for (int j = t; j < NTAB * 32; j += blockDim.x) {
            int e = j >> 5;               // 0..65
            float2 ts;
            if (e == 0)            { ts.x = x0 - h; ts.y = h;    }
            else if (e == NTAB-1)  { ts.x = 0.0f;   ts.y = 0.0f; }
            else                   { ts.x = y[e-1]; ts.y = y[e] - y[e-1]; }
            tab[j] = ts;
        }
        if (t == 0) { sc[0] = x0; sc[1] = xK; }
    }
    __syncthreads();

    const float x0    = sc[0];
    const float xK    = sc[1];
    const float inv_h = (float)NSEG / (xK - x0);
    const float off   = -x0 * inv_h;          // u = v*inv_h + off

    const float2* __restrict__ mytab = tab + (t & 31);

    const int n4 = n >> 2;
    const float4* __restrict__ v4 = (const float4*)vals;
    float4* __restrict__ o4 = (float4*)out;

    const int tid    = blockIdx.x * blockDim.x + t;
    const int stride = gridDim.x * blockDim.x;

    #define INTERP(V, O) do {                                           \
        float u  = fmaf((V), inv_h, off);                               \
        float uf = floorf(u);                                           \
        uf = fmaxf(-1.0f, fminf(uf, 64.0f));                            \
        float fr = u - uf;             /* unclamped: extends guards */  \
        int   e  = ((int)uf + 1) << 5; /* entry * 32 */                 \
        float2 ts = mytab[e];                                           \
        (O) = fmaf(fr, ts.y, ts.x);                                     \
    } while (0)

    #define DO4(A, OA)                                                  \
        INTERP((A).x, (OA).x); INTERP((A).y, (OA).y);                   \
        INTERP((A).z, (OA).z); INTERP((A).w, (OA).w);

    int i = tid;
    // 8x unrolled main loop: all 8 LDG.128 issued before any use
    for (; i + 7 * stride < n4; i += 8 * stride) {
        float4 a0 = __ldcs(&v4[i]);
        float4 a1 = __ldcs(&v4[i +     stride]);
        float4 a2 = __ldcs(&v4[i + 2 * stride]);
        float4 a3 = __ldcs(&v4[i + 3 * stride]);
        float4 a4 = __ldcs(&v4[i + 4 * stride]);
        float4 a5 = __ldcs(&v4[i + 5 * stride]);
        float4 a6 = __ldcs(&v4[i + 6 * stride]);
        float4 a7 = __ldcs(&v4[i + 7 * stride]);
        float4 o0, o1, o2, o3, o4v, o5, o6, o7;
        DO4(a0, o0); DO4(a1, o1); DO4(a2, o2); DO4(a3, o3);
        DO4(a4, o4v); DO4(a5, o5); DO4(a6, o6); DO4(a7, o7);
        __stcs(&o4[i],              o0);
        __stcs(&o4[i +     stride], o1);
        __stcs(&o4[i + 2 * stride], o2);
        __stcs(&o4[i + 3 * stride], o3);
        __stcs(&o4[i + 4 * stride], o4v);
        __stcs(&o4[i + 5 * stride], o5);
        __stcs(&o4[i + 6 * stride], o6);
        __stcs(&o4[i + 7 * stride], o7);
    }
    for (; i < n4; i += stride) {
        float4 a = __ldcs(&v4[i]);
        float4 oa;
        DO4(a, oa);
        __stcs(&o4[i], oa);
    }

    // scalar tail (n % 4 != 0 -- not hit for this shape, kept for safety)
    for (int j = (n4 << 2) + tid; j < n; j += stride) {
        float v = vals[j], o;
        INTERP(v, o);
        out[j] = o;
    }
    #undef DO4
    #undef INTERP
}

extern "C" void kernel_launch(void* const* d_in, const int* in_sizes, int n_in,
                              void* d_out, int out_size)
{
    const float* vals = (const float*)d_in[0];
    const float* x    = (const float*)d_in[1];
    const float* y    = (const float*)d_in[2];
    float* out        = (float*)d_out;
    int n = in_sizes[0];

    // one full wave at 5 CTAs/SM (48-reg build): 148 * 5 = 740 blocks
    int blocks = 740;
    logsig_pwl_kernel<<<blocks, 256>>>(vals, x, y, out, n);
}

// round 10
// speedup vs baseline: 1.0836x; 1.0764x over previous
#include <cuda_runtime.h>
#include <cuda_bf16.h>

// Piecewise-linear log-sigmoid approximation (uniform breakpoints), v8.
//
// v7 body (8x-unrolled grid-stride, all 8 LDG.128 batched up front, 48 regs
// via __launch_bounds__(256,5), conflict-free per-lane float2 LUT) with a
// multi-wave grid: 2960 blocks (~4 waves at 5 CTAs/SM) so the CLC work queue
// rebalances CTAs across fast/slow SMs instead of one straggler-bound wave.
//
// Index-space formulation (no branches): u = (v-x0)/h,
//   e = clamp(floor(u), -1, 64) + 1   (0..65)
//   out = Y[e] + (u - uf) * D[e]
// Guard entries: e=0 -> {x0-h, h} (exact identity for v < x0),
// e=65 -> {0,0} (zero for v >= xK).

#define NSEG  64
#define NBRK  65
#define NTAB  66          // entries for idx = -1 .. 64

__global__ __launch_bounds__(256, 5)
void logsig_pwl_kernel(const float* __restrict__ vals,
                       const float* __restrict__ x,
                       const float* __restrict__ y,
                       float* __restrict__ out,
                       int n)
{
    __shared__ float2 tab[NTAB * 32];   // [entry][lane] {y, dy}
    __shared__ float  sc[2];            // x0, xK

    const int t = threadIdx.x;

    {
        const float x0 = x[0];
        const float xK = x[NBRK - 1];
        const float h  = (xK - x0) * (1.0f / NSEG);
        for (int j = t; j < NTAB * 32; j += blockDim.x) {
            int e = j >> 5;               // 0..65
            float2 ts;
            if (e == 0)            { ts.x = x0 - h; ts.y = h;    }
            else if (e == NTAB-1)  { ts.x = 0.0f;   ts.y = 0.0f; }
            else                   { ts.x = y[e-1]; ts.y = y[e] - y[e-1]; }
            tab[j] = ts;
        }
        if (t == 0) { sc[0] = x0; sc[1] = xK; }
    }
    __syncthreads();

    const float x0    = sc[0];
    const float xK    = sc[1];
    const float inv_h = (float)NSEG / (xK - x0);
    const float off   = -x0 * inv_h;          // u = v*inv_h + off

    const float2* __restrict__ mytab = tab + (t & 31);

    const int n4 = n >> 2;
    const float4* __restrict__ v4 = (const float4*)vals;
    float4* __restrict__ o4 = (float4*)out;

    const int tid    = blockIdx.x * blockDim.x + t;
    const int stride = gridDim.x * blockDim.x;

    #define INTERP(V, O) do {                                           \
        float u  = fmaf((V), inv_h, off);                               \
        float uf = floorf(u);                                           \
        uf = fmaxf(-1.0f, fminf(uf, 64.0f));                            \
        float fr = u - uf;             /* unclamped: extends guards */  \
        int   e  = ((int)uf + 1) << 5; /* entry * 32 */                 \
        float2 ts = mytab[e];                                           \
        (O) = fmaf(fr, ts.y, ts.x);                                     \
    } while (0)

    #define DO4(A, OA)                                                  \
        INTERP((A).x, (OA).x); INTERP((A).y, (OA).y);                   \
        INTERP((A).z, (OA).z); INTERP((A).w, (OA).w);

    int i = tid;
    // 8x unrolled main loop: all 8 LDG.128 issued before any use
    for (; i + 7 * stride < n4; i += 8 * stride) {
        float4 a0 = __ldcs(&v4[i]);
        float4 a1 = __ldcs(&v4[i +     stride]);
        float4 a2 = __ldcs(&v4[i + 2 * stride]);
        float4 a3 = __ldcs(&v4[i + 3 * stride]);
        float4 a4 = __ldcs(&v4[i + 4 * stride]);
        float4 a5 = __ldcs(&v4[i + 5 * stride]);
        float4 a6 = __ldcs(&v4[i + 6 * stride]);
        float4 a7 = __ldcs(&v4[i + 7 * stride]);
        float4 o0, o1, o2, o3, o4v, o5, o6, o7;
        DO4(a0, o0); DO4(a1, o1); DO4(a2, o2); DO4(a3, o3);
        DO4(a4, o4v); DO4(a5, o5); DO4(a6, o6); DO4(a7, o7);
        __stcs(&o4[i],              o0);
        __stcs(&o4[i +     stride], o1);
        __stcs(&o4[i + 2 * stride], o2);
        __stcs(&o4[i + 3 * stride], o3);
        __stcs(&o4[i + 4 * stride], o4v);
        __stcs(&o4[i + 5 * stride], o5);
        __stcs(&o4[i + 6 * stride], o6);
        __stcs(&o4[i + 7 * stride], o7);
    }
    for (; i < n4; i += stride) {
        float4 a = __ldcs(&v4[i]);
        float4 oa;
        DO4(a, oa);
        __stcs(&o4[i], oa);
    }

    // scalar tail (n % 4 != 0 -- not hit for this shape, kept for safety)
    for (int j = (n4 << 2) + tid; j < n; j += stride) {
        float v = vals[j], o;
        INTERP(v, o);
        out[j] = o;
    }
    #undef DO4
    #undef INTERP
}

extern "C" void kernel_launch(void* const* d_in, const int* in_sizes, int n_in,
                              void* d_out, int out_size)
{
    const float* vals = (const float*)d_in[0];
    const float* x    = (const float*)d_in[1];
    const float* y    = (const float*)d_in[2];
    float* out        = (float*)d_out;
    int n = in_sizes[0];

    // ~4 waves at 5 CTAs/SM: CLC rebalances across fast/slow SMs,
    // shrinking the straggler tail vs a single exact-cover wave.
    int blocks = 2960;
    logsig_pwl_kernel<<<blocks, 256>>>(vals, x, y, out, n);
}